// round 12
// baseline (speedup 1.0000x reference)
#include <cuda_runtime.h>

#define Nn   16384
#define Ff   500
#define Ee   128
#define LINn 128
#define Cc   10
#define Bb   4096
#define CAP  128
#define KP   512      // zero-padded K for layer-1 GEMM
#define PADR 132      // smem row pad

// ----- scratch (device globals; no allocation allowed) -----
__device__ int   g_nbr[Nn * CAP];          // 8 MB  CSR neighbor indices
__device__ float g_deg[Nn];                // degrees
__device__ float g_Wt [KP * 256];          // [k][e'] : e'<128 self-part W1a, e'>=128 neigh-part W1b (k-major, zero padded)
__device__ float g_Y  [(size_t)Nn * 256];  // 16.8 MB  data @ [W1a^T | W1b^T]
__device__ float g_H1 [(size_t)Nn * Ee];   // 8.4 MB
__device__ float g_h2 [(size_t)Bb * 256];  // layer-2 input
__device__ float g_H2 [(size_t)Bb * Ee];
__device__ float g_W2t[256 * 128];         // W2 transposed (k-major)

// ----- packed fp32x2 helpers (Blackwell FFMA2 — 2x fp32 rate) -----
__device__ __forceinline__ unsigned long long pk2(float x, float y) {
    unsigned long long r;
    asm("mov.b64 %0, {%1, %2};" : "=l"(r) : "f"(x), "f"(y));
    return r;
}
__device__ __forceinline__ void fma2(unsigned long long &d, unsigned long long a, unsigned long long b) {
    asm("fma.rn.f32x2 %0, %1, %2, %0;" : "+l"(d) : "l"(a), "l"(b));
}
__device__ __forceinline__ float2 up2(unsigned long long v) {
    float2 r;
    asm("mov.b64 {%0, %1}, %2;" : "=f"(r.x), "=f"(r.y) : "l"(v));
    return r;
}

// ----- K0: weight repack (Wt padded/transposed, W2t transposed) -----
__global__ void prep_kernel(const float* __restrict__ W1, const float* __restrict__ W2) {
    int idx = blockIdx.x * blockDim.x + threadIdx.x;
    if (idx < KP * 256) {
        int k = idx >> 8, e = idx & 255;
        float v = 0.f;
        if (k < Ff) v = (e < Ee) ? W1[e * (2 * Ff) + k]
                                 : W1[(e - Ee) * (2 * Ff) + Ff + k];
        g_Wt[idx] = v;
    }
    if (idx < 256 * 128) {
        int k = idx >> 7, e = idx & 127;
        g_W2t[idx] = W2[e * 256 + k];
    }
}

// ----- K1 fused: blocks [0,256) = GEMM Y = data @ Wt ; blocks [256,...) = CSR build -----
__global__ __launch_bounds__(256, 2)
void scan_gemm_kernel(const float* __restrict__ adj, const float* __restrict__ data) {
    __shared__ __align__(16) float As[16][PADR];
    __shared__ __align__(16) float Bs[16][PADR];
    __shared__ int cnt;

    int tid = threadIdx.x;

    if (blockIdx.x >= 256) {
        // ---------- CSR scan of one adj row ----------
        int row = blockIdx.x - 256;
        if (tid == 0) cnt = 0;
        __syncthreads();
        const float4* rp = (const float4*)(adj + (size_t)row * Nn);
        int* nb = g_nbr + row * CAP;
        #pragma unroll 4
        for (int i = tid; i < Nn / 4; i += 256) {
            float4 v = rp[i];
            int c = i * 4;
            if (v.x != 0.f) { int p = atomicAdd(&cnt, 1); if (p < CAP) nb[p] = c;     }
            if (v.y != 0.f) { int p = atomicAdd(&cnt, 1); if (p < CAP) nb[p] = c + 1; }
            if (v.z != 0.f) { int p = atomicAdd(&cnt, 1); if (p < CAP) nb[p] = c + 2; }
            if (v.w != 0.f) { int p = atomicAdd(&cnt, 1); if (p < CAP) nb[p] = c + 3; }
        }
        __syncthreads();
        if (tid == 0) g_deg[row] = (float)cnt;
        return;
    }

    // ---------- GEMM block:  Y[128 rows][128 cols]  M=16384 N=256 K=512(padded) ----------
    int blk  = blockIdx.x;
    int bxc  = blk & 1;            // col block (0..1)
    int byr  = blk >> 1;           // row block (0..127)
    int row0 = byr * 128;
    int col0 = bxc * 128;
    int tm = tid >> 4, tn = tid & 15;

    unsigned long long acc[8][4];
    #pragma unroll
    for (int i = 0; i < 8; i++)
        #pragma unroll
        for (int j = 0; j < 4; j++) acc[i][j] = 0ull;

    int lr  = tid >> 2;            // 0..63  (A load: row)
    int lc  = (tid & 3) * 4;       // 0,4,8,12 (A load: k within tile)
    int bkk = tid >> 5;            // 0..7   (B load: k row)
    int bc  = (tid & 31) * 4;      // 0..124 (B load: col)

    for (int k0 = 0; k0 < KP; k0 += 16) {
        // load A tile (128x16) transposed into As[k][m]; zero-pad k>=500
        #pragma unroll
        for (int h = 0; h < 2; h++) {
            int r  = lr + h * 64;
            int kg = k0 + lc;
            float4 v = make_float4(0.f, 0.f, 0.f, 0.f);
            if (kg < Ff) v = *(const float4*)(data + (size_t)(row0 + r) * Ff + kg);
            As[lc + 0][r] = v.x; As[lc + 1][r] = v.y;
            As[lc + 2][r] = v.z; As[lc + 3][r] = v.w;
        }
        // load B tile (16x128)
        #pragma unroll
        for (int h = 0; h < 2; h++) {
            int kk = bkk + h * 8;
            *(float4*)&Bs[kk][bc] = *(const float4*)(g_Wt + (k0 + kk) * 256 + col0 + bc);
        }
        __syncthreads();
        #pragma unroll
        for (int kk = 0; kk < 16; kk++) {
            float4 a0 = *(float4*)&As[kk][tm * 8];
            float4 a1 = *(float4*)&As[kk][tm * 8 + 4];
            ulonglong2 b0 = *(ulonglong2*)&Bs[kk][tn * 4];
            ulonglong2 b1 = *(ulonglong2*)&Bs[kk][64 + tn * 4];
            unsigned long long pa[8];
            pa[0] = pk2(a0.x, a0.x); pa[1] = pk2(a0.y, a0.y);
            pa[2] = pk2(a0.z, a0.z); pa[3] = pk2(a0.w, a0.w);
            pa[4] = pk2(a1.x, a1.x); pa[5] = pk2(a1.y, a1.y);
            pa[6] = pk2(a1.z, a1.z); pa[7] = pk2(a1.w, a1.w);
            #pragma unroll
            for (int i = 0; i < 8; i++) {
                fma2(acc[i][0], pa[i], b0.x);
                fma2(acc[i][1], pa[i], b0.y);
                fma2(acc[i][2], pa[i], b1.x);
                fma2(acc[i][3], pa[i], b1.y);
            }
        }
        __syncthreads();
    }
    #pragma unroll
    for (int i = 0; i < 8; i++) {
        int r = row0 + tm * 8 + i;
        float2 c0 = up2(acc[i][0]), c1 = up2(acc[i][1]);
        float2 c2 = up2(acc[i][2]), c3 = up2(acc[i][3]);
        *(float4*)(g_Y + (size_t)r * 256 + col0 + tn * 4)      = make_float4(c0.x, c0.y, c1.x, c1.y);
        *(float4*)(g_Y + (size_t)r * 256 + col0 + 64 + tn * 4) = make_float4(c2.x, c2.y, c3.x, c3.y);
    }
}

// ----- K2: layer-1 aggregate + bias + relu + l2norm -> H1  (warp per node) -----
__global__ void agg1_kernel(const float* __restrict__ b1) {
    int warp = (blockIdx.x * blockDim.x + threadIdx.x) >> 5;
    int lane = threadIdx.x & 31;
    if (warp >= Nn) return;
    int n = warp;
    float d = g_deg[n];
    int c = (int)d; if (c > CAP) c = CAP;
    const int* nb = g_nbr + n * CAP;
    int c4 = lane * 4;
    float4 acc = make_float4(0.f, 0.f, 0.f, 0.f);
    for (int t = 0; t < c; t++) {
        int j = __ldg(nb + t);
        float4 v = *(const float4*)(g_Y + (size_t)j * 256 + 128 + c4);
        acc.x += v.x; acc.y += v.y; acc.z += v.z; acc.w += v.w;
    }
    float inv = 1.f / d;
    float4 self = *(const float4*)(g_Y + (size_t)n * 256 + c4);
    float4 bb   = *(const float4*)(b1 + c4);
    float4 p;
    p.x = fmaxf(fmaf(acc.x, inv, self.x) + bb.x, 0.f);
    p.y = fmaxf(fmaf(acc.y, inv, self.y) + bb.y, 0.f);
    p.z = fmaxf(fmaf(acc.z, inv, self.z) + bb.z, 0.f);
    p.w = fmaxf(fmaf(acc.w, inv, self.w) + bb.w, 0.f);
    float ss = p.x * p.x + p.y * p.y + p.z * p.z + p.w * p.w;
    #pragma unroll
    for (int o = 16; o > 0; o >>= 1) ss += __shfl_xor_sync(0xffffffffu, ss, o);
    float s = 1.f / fmaxf(sqrtf(ss), 1e-12f);
    p.x *= s; p.y *= s; p.z *= s; p.w *= s;
    *(float4*)(g_H1 + (size_t)n * Ee + c4) = p;
}

// ----- K3: gather h2 = [H1[node], agg(H1)/deg] for the batch (warp per node) -----
__global__ void gather2_kernel(const int* __restrict__ nodes) {
    int warp = (blockIdx.x * blockDim.x + threadIdx.x) >> 5;
    int lane = threadIdx.x & 31;
    if (warp >= Bb) return;
    int n = nodes[warp];
    int c4 = lane * 4;
    float4 self = *(const float4*)(g_H1 + (size_t)n * Ee + c4);
    *(float4*)(g_h2 + (size_t)warp * 256 + c4) = self;
    float d = g_deg[n];
    int c = (int)d; if (c > CAP) c = CAP;
    const int* nb = g_nbr + n * CAP;
    float4 acc = make_float4(0.f, 0.f, 0.f, 0.f);
    for (int t = 0; t < c; t++) {
        int j = __ldg(nb + t);
        float4 v = *(const float4*)(g_H1 + (size_t)j * Ee + c4);
        acc.x += v.x; acc.y += v.y; acc.z += v.z; acc.w += v.w;
    }
    float inv = 1.f / d;
    acc.x *= inv; acc.y *= inv; acc.z *= inv; acc.w *= inv;
    *(float4*)(g_h2 + (size_t)warp * 256 + 128 + c4) = acc;
}

// ----- K4: H2 = l2norm(relu(h2 @ W2^T + b2))   M=4096 N=128 K=256 -----
__global__ __launch_bounds__(256, 2)
void gemm2_kernel(const float* __restrict__ b2) {
    __shared__ __align__(16) float As[16][PADR];
    __shared__ __align__(16) float Bs[16][PADR];
    int tid = threadIdx.x;
    int tm = tid >> 4, tn = tid & 15;
    int row0 = blockIdx.y * 128;

    unsigned long long acc[8][4];
    #pragma unroll
    for (int i = 0; i < 8; i++)
        #pragma unroll
        for (int j = 0; j < 4; j++) acc[i][j] = 0ull;

    int lr  = tid >> 2;
    int lc  = (tid & 3) * 4;
    int bkk = tid >> 5;
    int bc  = (tid & 31) * 4;

    for (int k0 = 0; k0 < 256; k0 += 16) {
        #pragma unroll
        for (int h = 0; h < 2; h++) {
            int r = lr + h * 64;
            float4 v = *(const float4*)(g_h2 + (size_t)(row0 + r) * 256 + k0 + lc);
            As[lc + 0][r] = v.x; As[lc + 1][r] = v.y;
            As[lc + 2][r] = v.z; As[lc + 3][r] = v.w;
        }
        #pragma unroll
        for (int h = 0; h < 2; h++) {
            int kk = bkk + h * 8;
            *(float4*)&Bs[kk][bc] = *(const float4*)(g_W2t + (k0 + kk) * 128 + bc);
        }
        __syncthreads();
        #pragma unroll
        for (int kk = 0; kk < 16; kk++) {
            float4 a0 = *(float4*)&As[kk][tm * 8];
            float4 a1 = *(float4*)&As[kk][tm * 8 + 4];
            ulonglong2 b0 = *(ulonglong2*)&Bs[kk][tn * 4];
            ulonglong2 b1 = *(ulonglong2*)&Bs[kk][64 + tn * 4];
            unsigned long long pa[8];
            pa[0] = pk2(a0.x, a0.x); pa[1] = pk2(a0.y, a0.y);
            pa[2] = pk2(a0.z, a0.z); pa[3] = pk2(a0.w, a0.w);
            pa[4] = pk2(a1.x, a1.x); pa[5] = pk2(a1.y, a1.y);
            pa[6] = pk2(a1.z, a1.z); pa[7] = pk2(a1.w, a1.w);
            #pragma unroll
            for (int i = 0; i < 8; i++) {
                fma2(acc[i][0], pa[i], b0.x);
                fma2(acc[i][1], pa[i], b0.y);
                fma2(acc[i][2], pa[i], b1.x);
                fma2(acc[i][3], pa[i], b1.y);
            }
        }
        __syncthreads();
    }
    // epilogue: +b2, relu, l2norm per row (reduce across the 16 tn lanes), store
    float4 b2a = *(const float4*)(b2 + tn * 4);
    float4 b2b = *(const float4*)(b2 + 64 + tn * 4);
    #pragma unroll
    for (int i = 0; i < 8; i++) {
        float2 c0 = up2(acc[i][0]), c1 = up2(acc[i][1]);
        float2 c2 = up2(acc[i][2]), c3 = up2(acc[i][3]);
        float v[8];
        v[0] = fmaxf(c0.x + b2a.x, 0.f); v[1] = fmaxf(c0.y + b2a.y, 0.f);
        v[2] = fmaxf(c1.x + b2a.z, 0.f); v[3] = fmaxf(c1.y + b2a.w, 0.f);
        v[4] = fmaxf(c2.x + b2b.x, 0.f); v[5] = fmaxf(c2.y + b2b.y, 0.f);
        v[6] = fmaxf(c3.x + b2b.z, 0.f); v[7] = fmaxf(c3.y + b2b.w, 0.f);
        float ss = 0.f;
        #pragma unroll
        for (int q = 0; q < 8; q++) ss += v[q] * v[q];
        ss += __shfl_xor_sync(0xffffffffu, ss, 1);
        ss += __shfl_xor_sync(0xffffffffu, ss, 2);
        ss += __shfl_xor_sync(0xffffffffu, ss, 4);
        ss += __shfl_xor_sync(0xffffffffu, ss, 8);
        float s = 1.f / fmaxf(sqrtf(ss), 1e-12f);
        int r = row0 + tm * 8 + i;
        *(float4*)(g_H2 + (size_t)r * Ee + tn * 4)      = make_float4(v[0]*s, v[1]*s, v[2]*s, v[3]*s);
        *(float4*)(g_H2 + (size_t)r * Ee + 64 + tn * 4) = make_float4(v[4]*s, v[5]*s, v[6]*s, v[7]*s);
    }
}

// ----- K5: classifier + softmax (block per batch node) -----
__global__ void cls_kernel(const float* __restrict__ Wl1, const float* __restrict__ bl1,
                           const float* __restrict__ Wl2, const float* __restrict__ bl2,
                           float* __restrict__ out) {
    __shared__ __align__(16) float Hs[Ee];
    __shared__ __align__(16) float xs[LINn];
    __shared__ float ls[Cc];
    int b = blockIdx.x;
    int t = threadIdx.x;
    Hs[t] = g_H2[(size_t)b * Ee + t];
    __syncthreads();
    float acc = bl1[t];
    const float4* wr = (const float4*)(Wl1 + t * Ee);
    const float4* hr = (const float4*)Hs;
    #pragma unroll
    for (int k = 0; k < Ee / 4; k++) {
        float4 w = wr[k]; float4 h = hr[k];
        acc += w.x * h.x + w.y * h.y + w.z * h.z + w.w * h.w;
    }
    xs[t] = acc;
    __syncthreads();
    if (t < Cc) {
        float a2 = bl2[t];
        const float4* w2 = (const float4*)(Wl2 + t * LINn);
        const float4* xr = (const float4*)xs;
        #pragma unroll
        for (int k = 0; k < LINn / 4; k++) {
            float4 w = w2[k]; float4 h = xr[k];
            a2 += w.x * h.x + w.y * h.y + w.z * h.z + w.w * h.w;
        }
        ls[t] = a2;
    }
    __syncthreads();
    if (t < Cc) {
        float m = ls[0];
        #pragma unroll
        for (int i = 1; i < Cc; i++) m = fmaxf(m, ls[i]);
        float s = 0.f;
        #pragma unroll
        for (int i = 0; i < Cc; i++) s += expf(ls[i] - m);
        out[(size_t)b * Cc + t] = expf(ls[t] - m) / s;
    }
}

extern "C" void kernel_launch(void* const* d_in, const int* in_sizes, int n_in,
                              void* d_out, int out_size) {
    const int*   nodes = (const int*)  d_in[0];
    const float* adj   = (const float*)d_in[1];
    const float* data  = (const float*)d_in[2];
    const float* W1    = (const float*)d_in[3];
    const float* b1    = (const float*)d_in[4];
    const float* W2    = (const float*)d_in[5];
    const float* b2    = (const float*)d_in[6];
    const float* Wl1   = (const float*)d_in[7];
    const float* bl1   = (const float*)d_in[8];
    const float* Wl2   = (const float*)d_in[9];
    const float* bl2   = (const float*)d_in[10];
    float* out = (float*)d_out;

    prep_kernel<<<512, 256>>>(W1, W2);
    scan_gemm_kernel<<<Nn + 256, 256>>>(adj, data);   // GEMM blocks [0,256) overlap CSR scan
    agg1_kernel<<<Nn / 8, 256>>>(b1);
    gather2_kernel<<<Bb / 8, 256>>>(nodes);
    gemm2_kernel<<<dim3(1, 32), 256>>>(b2);
    cls_kernel<<<Bb, 128>>>(Wl1, bl1, Wl2, bl2, out);
}

// round 13
// speedup vs baseline: 1.0055x; 1.0055x over previous
#include <cuda_runtime.h>

#define Nn   16384
#define Ff   500
#define Ee   128
#define LINn 128
#define Cc   10
#define Bb   4096
#define CAP  128
#define KP   512      // zero-padded K for layer-1 GEMM
#define PADR 132      // smem row pad

// ----- scratch (device globals; no allocation allowed) -----
__device__ int   g_nbr[Nn * CAP];          // 8 MB  CSR neighbor indices
__device__ float g_deg[Nn];                // degrees
__device__ float g_Wt [KP * 256];          // [k][e'] : e'<128 self-part W1a, e'>=128 neigh-part W1b (k-major, zero padded)
__device__ float g_Y  [(size_t)Nn * 256];  // 16.8 MB  data @ [W1a^T | W1b^T]
__device__ float g_H1 [(size_t)Nn * Ee];   // 8.4 MB
__device__ float g_h2 [(size_t)Bb * 256];  // layer-2 input
__device__ float g_H2 [(size_t)Bb * Ee];
__device__ float g_W2t[256 * 128];         // W2 transposed (k-major)

// ----- packed fp32x2 helpers (Blackwell FFMA2 — 2x fp32 rate) -----
__device__ __forceinline__ unsigned long long pk2(float x, float y) {
    unsigned long long r;
    asm("mov.b64 %0, {%1, %2};" : "=l"(r) : "f"(x), "f"(y));
    return r;
}
__device__ __forceinline__ void fma2(unsigned long long &d, unsigned long long a, unsigned long long b) {
    asm("fma.rn.f32x2 %0, %1, %2, %0;" : "+l"(d) : "l"(a), "l"(b));
}
__device__ __forceinline__ float2 up2(unsigned long long v) {
    float2 r;
    asm("mov.b64 {%0, %1}, %2;" : "=f"(r.x), "=f"(r.y) : "l"(v));
    return r;
}

// ----- K0: weight repack (Wt padded/transposed, W2t transposed) -----
__global__ void prep_kernel(const float* __restrict__ W1, const float* __restrict__ W2) {
    int idx = blockIdx.x * blockDim.x + threadIdx.x;
    if (idx < KP * 256) {
        int k = idx >> 8, e = idx & 255;
        float v = 0.f;
        if (k < Ff) v = (e < Ee) ? W1[e * (2 * Ff) + k]
                                 : W1[(e - Ee) * (2 * Ff) + Ff + k];
        g_Wt[idx] = v;
    }
    if (idx < 256 * 128) {
        int k = idx >> 7, e = idx & 127;
        g_W2t[idx] = W2[e * 256 + k];
    }
}

// ----- K1 fused: blocks [0,256) = GEMM Y = data @ Wt ; blocks [256,...) = CSR build -----
__global__ __launch_bounds__(256, 2)
void scan_gemm_kernel(const float* __restrict__ adj, const float* __restrict__ data) {
    __shared__ __align__(16) float As[16][PADR];
    __shared__ __align__(16) float Bs[16][PADR];
    __shared__ int cnt;

    int tid = threadIdx.x;

    if (blockIdx.x >= 256) {
        // ---------- CSR scan of one adj row ----------
        int row = blockIdx.x - 256;
        if (tid == 0) cnt = 0;
        __syncthreads();
        const float4* rp = (const float4*)(adj + (size_t)row * Nn);
        int* nb = g_nbr + row * CAP;
        #pragma unroll 4
        for (int i = tid; i < Nn / 4; i += 256) {
            float4 v = rp[i];
            int c = i * 4;
            if (v.x != 0.f) { int p = atomicAdd(&cnt, 1); if (p < CAP) nb[p] = c;     }
            if (v.y != 0.f) { int p = atomicAdd(&cnt, 1); if (p < CAP) nb[p] = c + 1; }
            if (v.z != 0.f) { int p = atomicAdd(&cnt, 1); if (p < CAP) nb[p] = c + 2; }
            if (v.w != 0.f) { int p = atomicAdd(&cnt, 1); if (p < CAP) nb[p] = c + 3; }
        }
        __syncthreads();
        if (tid == 0) g_deg[row] = (float)cnt;
        return;
    }

    // ---------- GEMM block:  Y[128 rows][128 cols]  M=16384 N=256 K=512(padded) ----------
    int blk  = blockIdx.x;
    int bxc  = blk & 1;            // col block (0..1)
    int byr  = blk >> 1;           // row block (0..127)
    int row0 = byr * 128;
    int col0 = bxc * 128;
    int tm = tid >> 4, tn = tid & 15;

    unsigned long long acc[8][4];
    #pragma unroll
    for (int i = 0; i < 8; i++)
        #pragma unroll
        for (int j = 0; j < 4; j++) acc[i][j] = 0ull;

    int lr  = tid >> 2;            // 0..63  (A load: row)
    int lc  = (tid & 3) * 4;       // 0,4,8,12 (A load: k within tile)
    int bkk = tid >> 5;            // 0..7   (B load: k row)
    int bc  = (tid & 31) * 4;      // 0..124 (B load: col)

    for (int k0 = 0; k0 < KP; k0 += 16) {
        // load A tile (128x16) transposed into As[k][m]; zero-pad k>=500
        #pragma unroll
        for (int h = 0; h < 2; h++) {
            int r  = lr + h * 64;
            int kg = k0 + lc;
            float4 v = make_float4(0.f, 0.f, 0.f, 0.f);
            if (kg < Ff) v = *(const float4*)(data + (size_t)(row0 + r) * Ff + kg);
            As[lc + 0][r] = v.x; As[lc + 1][r] = v.y;
            As[lc + 2][r] = v.z; As[lc + 3][r] = v.w;
        }
        // load B tile (16x128)
        #pragma unroll
        for (int h = 0; h < 2; h++) {
            int kk = bkk + h * 8;
            *(float4*)&Bs[kk][bc] = *(const float4*)(g_Wt + (k0 + kk) * 256 + col0 + bc);
        }
        __syncthreads();
        #pragma unroll
        for (int kk = 0; kk < 16; kk++) {
            float4 a0 = *(float4*)&As[kk][tm * 8];
            float4 a1 = *(float4*)&As[kk][tm * 8 + 4];
            ulonglong2 b0 = *(ulonglong2*)&Bs[kk][tn * 4];
            ulonglong2 b1 = *(ulonglong2*)&Bs[kk][64 + tn * 4];
            unsigned long long pa[8];
            pa[0] = pk2(a0.x, a0.x); pa[1] = pk2(a0.y, a0.y);
            pa[2] = pk2(a0.z, a0.z); pa[3] = pk2(a0.w, a0.w);
            pa[4] = pk2(a1.x, a1.x); pa[5] = pk2(a1.y, a1.y);
            pa[6] = pk2(a1.z, a1.z); pa[7] = pk2(a1.w, a1.w);
            #pragma unroll
            for (int i = 0; i < 8; i++) {
                fma2(acc[i][0], pa[i], b0.x);
                fma2(acc[i][1], pa[i], b0.y);
                fma2(acc[i][2], pa[i], b1.x);
                fma2(acc[i][3], pa[i], b1.y);
            }
        }
        __syncthreads();
    }
    #pragma unroll
    for (int i = 0; i < 8; i++) {
        int r = row0 + tm * 8 + i;
        float2 c0 = up2(acc[i][0]), c1 = up2(acc[i][1]);
        float2 c2 = up2(acc[i][2]), c3 = up2(acc[i][3]);
        *(float4*)(g_Y + (size_t)r * 256 + col0 + tn * 4)      = make_float4(c0.x, c0.y, c1.x, c1.y);
        *(float4*)(g_Y + (size_t)r * 256 + col0 + 64 + tn * 4) = make_float4(c2.x, c2.y, c3.x, c3.y);
    }
}

// ----- K2: layer-1 aggregate + bias + relu + l2norm -> H1  (warp per node) -----
__global__ void agg1_kernel(const float* __restrict__ b1) {
    int warp = (blockIdx.x * blockDim.x + threadIdx.x) >> 5;
    int lane = threadIdx.x & 31;
    if (warp >= Nn) return;
    int n = warp;
    float d = g_deg[n];
    int c = (int)d; if (c > CAP) c = CAP;
    const int* nb = g_nbr + n * CAP;
    int c4 = lane * 4;
    float4 acc = make_float4(0.f, 0.f, 0.f, 0.f);
    for (int t = 0; t < c; t++) {
        int j = __ldg(nb + t);
        float4 v = *(const float4*)(g_Y + (size_t)j * 256 + 128 + c4);
        acc.x += v.x; acc.y += v.y; acc.z += v.z; acc.w += v.w;
    }
    float inv = 1.f / d;
    float4 self = *(const float4*)(g_Y + (size_t)n * 256 + c4);
    float4 bb   = *(const float4*)(b1 + c4);
    float4 p;
    p.x = fmaxf(fmaf(acc.x, inv, self.x) + bb.x, 0.f);
    p.y = fmaxf(fmaf(acc.y, inv, self.y) + bb.y, 0.f);
    p.z = fmaxf(fmaf(acc.z, inv, self.z) + bb.z, 0.f);
    p.w = fmaxf(fmaf(acc.w, inv, self.w) + bb.w, 0.f);
    float ss = p.x * p.x + p.y * p.y + p.z * p.z + p.w * p.w;
    #pragma unroll
    for (int o = 16; o > 0; o >>= 1) ss += __shfl_xor_sync(0xffffffffu, ss, o);
    float s = 1.f / fmaxf(sqrtf(ss), 1e-12f);
    p.x *= s; p.y *= s; p.z *= s; p.w *= s;
    *(float4*)(g_H1 + (size_t)n * Ee + c4) = p;
}

// ----- K3: gather h2 = [H1[node], agg(H1)/deg] for the batch (warp per node) -----
__global__ void gather2_kernel(const int* __restrict__ nodes) {
    int warp = (blockIdx.x * blockDim.x + threadIdx.x) >> 5;
    int lane = threadIdx.x & 31;
    if (warp >= Bb) return;
    int n = nodes[warp];
    int c4 = lane * 4;
    float4 self = *(const float4*)(g_H1 + (size_t)n * Ee + c4);
    *(float4*)(g_h2 + (size_t)warp * 256 + c4) = self;
    float d = g_deg[n];
    int c = (int)d; if (c > CAP) c = CAP;
    const int* nb = g_nbr + n * CAP;
    float4 acc = make_float4(0.f, 0.f, 0.f, 0.f);
    for (int t = 0; t < c; t++) {
        int j = __ldg(nb + t);
        float4 v = *(const float4*)(g_H1 + (size_t)j * Ee + c4);
        acc.x += v.x; acc.y += v.y; acc.z += v.z; acc.w += v.w;
    }
    float inv = 1.f / d;
    acc.x *= inv; acc.y *= inv; acc.z *= inv; acc.w *= inv;
    *(float4*)(g_h2 + (size_t)warp * 256 + 128 + c4) = acc;
}

// ----- K4: H2 = l2norm(relu(h2 @ W2^T + b2))   M=4096 N=128 K=256 -----
__global__ __launch_bounds__(256, 2)
void gemm2_kernel(const float* __restrict__ b2) {
    __shared__ __align__(16) float As[16][PADR];
    __shared__ __align__(16) float Bs[16][PADR];
    int tid = threadIdx.x;
    int tm = tid >> 4, tn = tid & 15;
    int row0 = blockIdx.y * 128;

    unsigned long long acc[8][4];
    #pragma unroll
    for (int i = 0; i < 8; i++)
        #pragma unroll
        for (int j = 0; j < 4; j++) acc[i][j] = 0ull;

    int lr  = tid >> 2;
    int lc  = (tid & 3) * 4;
    int bkk = tid >> 5;
    int bc  = (tid & 31) * 4;

    for (int k0 = 0; k0 < 256; k0 += 16) {
        #pragma unroll
        for (int h = 0; h < 2; h++) {
            int r = lr + h * 64;
            float4 v = *(const float4*)(g_h2 + (size_t)(row0 + r) * 256 + k0 + lc);
            As[lc + 0][r] = v.x; As[lc + 1][r] = v.y;
            As[lc + 2][r] = v.z; As[lc + 3][r] = v.w;
        }
        #pragma unroll
        for (int h = 0; h < 2; h++) {
            int kk = bkk + h * 8;
            *(float4*)&Bs[kk][bc] = *(const float4*)(g_W2t + (k0 + kk) * 128 + bc);
        }
        __syncthreads();
        #pragma unroll
        for (int kk = 0; kk < 16; kk++) {
            float4 a0 = *(float4*)&As[kk][tm * 8];
            float4 a1 = *(float4*)&As[kk][tm * 8 + 4];
            ulonglong2 b0 = *(ulonglong2*)&Bs[kk][tn * 4];
            ulonglong2 b1 = *(ulonglong2*)&Bs[kk][64 + tn * 4];
            unsigned long long pa[8];
            pa[0] = pk2(a0.x, a0.x); pa[1] = pk2(a0.y, a0.y);
            pa[2] = pk2(a0.z, a0.z); pa[3] = pk2(a0.w, a0.w);
            pa[4] = pk2(a1.x, a1.x); pa[5] = pk2(a1.y, a1.y);
            pa[6] = pk2(a1.z, a1.z); pa[7] = pk2(a1.w, a1.w);
            #pragma unroll
            for (int i = 0; i < 8; i++) {
                fma2(acc[i][0], pa[i], b0.x);
                fma2(acc[i][1], pa[i], b0.y);
                fma2(acc[i][2], pa[i], b1.x);
                fma2(acc[i][3], pa[i], b1.y);
            }
        }
        __syncthreads();
    }
    // epilogue: +b2, relu, l2norm per row (reduce across the 16 tn lanes), store
    float4 b2a = *(const float4*)(b2 + tn * 4);
    float4 b2b = *(const float4*)(b2 + 64 + tn * 4);
    #pragma unroll
    for (int i = 0; i < 8; i++) {
        float2 c0 = up2(acc[i][0]), c1 = up2(acc[i][1]);
        float2 c2 = up2(acc[i][2]), c3 = up2(acc[i][3]);
        float v[8];
        v[0] = fmaxf(c0.x + b2a.x, 0.f); v[1] = fmaxf(c0.y + b2a.y, 0.f);
        v[2] = fmaxf(c1.x + b2a.z, 0.f); v[3] = fmaxf(c1.y + b2a.w, 0.f);
        v[4] = fmaxf(c2.x + b2b.x, 0.f); v[5] = fmaxf(c2.y + b2b.y, 0.f);
        v[6] = fmaxf(c3.x + b2b.z, 0.f); v[7] = fmaxf(c3.y + b2b.w, 0.f);
        float ss = 0.f;
        #pragma unroll
        for (int q = 0; q < 8; q++) ss += v[q] * v[q];
        ss += __shfl_xor_sync(0xffffffffu, ss, 1);
        ss += __shfl_xor_sync(0xffffffffu, ss, 2);
        ss += __shfl_xor_sync(0xffffffffu, ss, 4);
        ss += __shfl_xor_sync(0xffffffffu, ss, 8);
        float s = 1.f / fmaxf(sqrtf(ss), 1e-12f);
        int r = row0 + tm * 8 + i;
        *(float4*)(g_H2 + (size_t)r * Ee + tn * 4)      = make_float4(v[0]*s, v[1]*s, v[2]*s, v[3]*s);
        *(float4*)(g_H2 + (size_t)r * Ee + 64 + tn * 4) = make_float4(v[4]*s, v[5]*s, v[6]*s, v[7]*s);
    }
}

// ----- K5: classifier + softmax (block per batch node) -----
__global__ void cls_kernel(const float* __restrict__ Wl1, const float* __restrict__ bl1,
                           const float* __restrict__ Wl2, const float* __restrict__ bl2,
                           float* __restrict__ out) {
    __shared__ __align__(16) float Hs[Ee];
    __shared__ __align__(16) float xs[LINn];
    __shared__ float ls[Cc];
    int b = blockIdx.x;
    int t = threadIdx.x;
    Hs[t] = g_H2[(size_t)b * Ee + t];
    __syncthreads();
    float acc = bl1[t];
    const float4* wr = (const float4*)(Wl1 + t * Ee);
    const float4* hr = (const float4*)Hs;
    #pragma unroll
    for (int k = 0; k < Ee / 4; k++) {
        float4 w = wr[k]; float4 h = hr[k];
        acc += w.x * h.x + w.y * h.y + w.z * h.z + w.w * h.w;
    }
    xs[t] = acc;
    __syncthreads();
    if (t < Cc) {
        float a2 = bl2[t];
        const float4* w2 = (const float4*)(Wl2 + t * LINn);
        const float4* xr = (const float4*)xs;
        #pragma unroll
        for (int k = 0; k < LINn / 4; k++) {
            float4 w = w2[k]; float4 h = xr[k];
            a2 += w.x * h.x + w.y * h.y + w.z * h.z + w.w * h.w;
        }
        ls[t] = a2;
    }
    __syncthreads();
    if (t < Cc) {
        float m = ls[0];
        #pragma unroll
        for (int i = 1; i < Cc; i++) m = fmaxf(m, ls[i]);
        float s = 0.f;
        #pragma unroll
        for (int i = 0; i < Cc; i++) s += expf(ls[i] - m);
        out[(size_t)b * Cc + t] = expf(ls[t] - m) / s;
    }
}

extern "C" void kernel_launch(void* const* d_in, const int* in_sizes, int n_in,
                              void* d_out, int out_size) {
    const int*   nodes = (const int*)  d_in[0];
    const float* adj   = (const float*)d_in[1];
    const float* data  = (const float*)d_in[2];
    const float* W1    = (const float*)d_in[3];
    const float* b1    = (const float*)d_in[4];
    const float* W2    = (const float*)d_in[5];
    const float* b2    = (const float*)d_in[6];
    const float* Wl1   = (const float*)d_in[7];
    const float* bl1   = (const float*)d_in[8];
    const float* Wl2   = (const float*)d_in[9];
    const float* bl2   = (const float*)d_in[10];
    float* out = (float*)d_out;

    prep_kernel<<<512, 256>>>(W1, W2);
    scan_gemm_kernel<<<Nn + 256, 256>>>(adj, data);   // GEMM blocks [0,256) overlap CSR scan
    agg1_kernel<<<Nn / 8, 256>>>(b1);
    gather2_kernel<<<Bb / 8, 256>>>(nodes);
    gemm2_kernel<<<dim3(1, 32), 256>>>(b2);
    cls_kernel<<<Bb, 128>>>(Wl1, bl1, Wl2, bl2, out);
}

// round 14
// speedup vs baseline: 1.0058x; 1.0003x over previous
#include <cuda_runtime.h>

#define Nn   16384
#define Ff   500
#define Ee   128
#define LINn 128
#define Cc   10
#define Bb   4096
#define CAP  128
#define KP   512      // zero-padded K for layer-1 GEMM
#define PADR 132      // smem row pad

// ----- scratch (device globals; no allocation allowed) -----
__device__ int   g_nbr[Nn * CAP];          // 8 MB  CSR neighbor indices
__device__ float g_deg[Nn];                // degrees
__device__ float g_Wt [KP * 256];          // [k][e'] : e'<128 self-part W1a, e'>=128 neigh-part W1b (k-major, zero padded)
__device__ float g_Y  [(size_t)Nn * 256];  // 16.8 MB  data @ [W1a^T | W1b^T]
__device__ float g_H1 [(size_t)Nn * Ee];   // 8.4 MB
__device__ float g_h2 [(size_t)Bb * 256];  // layer-2 input
__device__ float g_H2 [(size_t)Bb * Ee];
__device__ float g_W2t[256 * 128];         // W2 transposed (k-major)

// ----- packed fp32x2 helpers (Blackwell FFMA2 — 2x fp32 rate) -----
__device__ __forceinline__ unsigned long long pk2(float x, float y) {
    unsigned long long r;
    asm("mov.b64 %0, {%1, %2};" : "=l"(r) : "f"(x), "f"(y));
    return r;
}
__device__ __forceinline__ void fma2(unsigned long long &d, unsigned long long a, unsigned long long b) {
    asm("fma.rn.f32x2 %0, %1, %2, %0;" : "+l"(d) : "l"(a), "l"(b));
}
__device__ __forceinline__ float2 up2(unsigned long long v) {
    float2 r;
    asm("mov.b64 {%0, %1}, %2;" : "=f"(r.x), "=f"(r.y) : "l"(v));
    return r;
}

// ----- K0: weight repack (Wt padded/transposed, W2t transposed) -----
__global__ void prep_kernel(const float* __restrict__ W1, const float* __restrict__ W2) {
    int idx = blockIdx.x * blockDim.x + threadIdx.x;
    if (idx < KP * 256) {
        int k = idx >> 8, e = idx & 255;
        float v = 0.f;
        if (k < Ff) v = (e < Ee) ? W1[e * (2 * Ff) + k]
                                 : W1[(e - Ee) * (2 * Ff) + Ff + k];
        g_Wt[idx] = v;
    }
    if (idx < 256 * 128) {
        int k = idx >> 7, e = idx & 127;
        g_W2t[idx] = W2[e * 256 + k];
    }
}

// ----- K1 fused: blocks [0,256) = GEMM Y = data @ Wt ; blocks [256,...) = CSR build -----
__global__ __launch_bounds__(256, 2)
void scan_gemm_kernel(const float* __restrict__ adj, const float* __restrict__ data) {
    __shared__ __align__(16) float As[16][PADR];
    __shared__ __align__(16) float Bs[16][PADR];
    __shared__ int cnt;

    int tid = threadIdx.x;

    if (blockIdx.x >= 256) {
        // ---------- CSR scan of one adj row ----------
        int row = blockIdx.x - 256;
        if (tid == 0) cnt = 0;
        __syncthreads();
        const float4* rp = (const float4*)(adj + (size_t)row * Nn);
        int* nb = g_nbr + row * CAP;
        #pragma unroll 4
        for (int i = tid; i < Nn / 4; i += 256) {
            float4 v = rp[i];
            int c = i * 4;
            if (v.x != 0.f) { int p = atomicAdd(&cnt, 1); if (p < CAP) nb[p] = c;     }
            if (v.y != 0.f) { int p = atomicAdd(&cnt, 1); if (p < CAP) nb[p] = c + 1; }
            if (v.z != 0.f) { int p = atomicAdd(&cnt, 1); if (p < CAP) nb[p] = c + 2; }
            if (v.w != 0.f) { int p = atomicAdd(&cnt, 1); if (p < CAP) nb[p] = c + 3; }
        }
        __syncthreads();
        if (tid == 0) g_deg[row] = (float)cnt;
        return;
    }

    // ---------- GEMM block:  Y[128 rows][128 cols]  M=16384 N=256 K=512(padded) ----------
    int blk  = blockIdx.x;
    int bxc  = blk & 1;            // col block (0..1)
    int byr  = blk >> 1;           // row block (0..127)
    int row0 = byr * 128;
    int col0 = bxc * 128;
    int tm = tid >> 4, tn = tid & 15;

    unsigned long long acc[8][4];
    #pragma unroll
    for (int i = 0; i < 8; i++)
        #pragma unroll
        for (int j = 0; j < 4; j++) acc[i][j] = 0ull;

    int lr  = tid >> 2;            // 0..63  (A load: row)
    int lc  = (tid & 3) * 4;       // 0,4,8,12 (A load: k within tile)
    int bkk = tid >> 5;            // 0..7   (B load: k row)
    int bc  = (tid & 31) * 4;      // 0..124 (B load: col)

    for (int k0 = 0; k0 < KP; k0 += 16) {
        // load A tile (128x16) transposed into As[k][m]; zero-pad k>=500
        #pragma unroll
        for (int h = 0; h < 2; h++) {
            int r  = lr + h * 64;
            int kg = k0 + lc;
            float4 v = make_float4(0.f, 0.f, 0.f, 0.f);
            if (kg < Ff) v = *(const float4*)(data + (size_t)(row0 + r) * Ff + kg);
            As[lc + 0][r] = v.x; As[lc + 1][r] = v.y;
            As[lc + 2][r] = v.z; As[lc + 3][r] = v.w;
        }
        // load B tile (16x128)
        #pragma unroll
        for (int h = 0; h < 2; h++) {
            int kk = bkk + h * 8;
            *(float4*)&Bs[kk][bc] = *(const float4*)(g_Wt + (k0 + kk) * 256 + col0 + bc);
        }
        __syncthreads();
        #pragma unroll
        for (int kk = 0; kk < 16; kk++) {
            float4 a0 = *(float4*)&As[kk][tm * 8];
            float4 a1 = *(float4*)&As[kk][tm * 8 + 4];
            ulonglong2 b0 = *(ulonglong2*)&Bs[kk][tn * 4];
            ulonglong2 b1 = *(ulonglong2*)&Bs[kk][64 + tn * 4];
            unsigned long long pa[8];
            pa[0] = pk2(a0.x, a0.x); pa[1] = pk2(a0.y, a0.y);
            pa[2] = pk2(a0.z, a0.z); pa[3] = pk2(a0.w, a0.w);
            pa[4] = pk2(a1.x, a1.x); pa[5] = pk2(a1.y, a1.y);
            pa[6] = pk2(a1.z, a1.z); pa[7] = pk2(a1.w, a1.w);
            #pragma unroll
            for (int i = 0; i < 8; i++) {
                fma2(acc[i][0], pa[i], b0.x);
                fma2(acc[i][1], pa[i], b0.y);
                fma2(acc[i][2], pa[i], b1.x);
                fma2(acc[i][3], pa[i], b1.y);
            }
        }
        __syncthreads();
    }
    #pragma unroll
    for (int i = 0; i < 8; i++) {
        int r = row0 + tm * 8 + i;
        float2 c0 = up2(acc[i][0]), c1 = up2(acc[i][1]);
        float2 c2 = up2(acc[i][2]), c3 = up2(acc[i][3]);
        *(float4*)(g_Y + (size_t)r * 256 + col0 + tn * 4)      = make_float4(c0.x, c0.y, c1.x, c1.y);
        *(float4*)(g_Y + (size_t)r * 256 + col0 + 64 + tn * 4) = make_float4(c2.x, c2.y, c3.x, c3.y);
    }
}

// ----- K2: layer-1 aggregate + bias + relu + l2norm -> H1  (warp per node) -----
__global__ void agg1_kernel(const float* __restrict__ b1) {
    int warp = (blockIdx.x * blockDim.x + threadIdx.x) >> 5;
    int lane = threadIdx.x & 31;
    if (warp >= Nn) return;
    int n = warp;
    float d = g_deg[n];
    int c = (int)d; if (c > CAP) c = CAP;
    const int* nb = g_nbr + n * CAP;
    int c4 = lane * 4;
    float4 acc = make_float4(0.f, 0.f, 0.f, 0.f);
    for (int t = 0; t < c; t++) {
        int j = __ldg(nb + t);
        float4 v = *(const float4*)(g_Y + (size_t)j * 256 + 128 + c4);
        acc.x += v.x; acc.y += v.y; acc.z += v.z; acc.w += v.w;
    }
    float inv = 1.f / d;
    float4 self = *(const float4*)(g_Y + (size_t)n * 256 + c4);
    float4 bb   = *(const float4*)(b1 + c4);
    float4 p;
    p.x = fmaxf(fmaf(acc.x, inv, self.x) + bb.x, 0.f);
    p.y = fmaxf(fmaf(acc.y, inv, self.y) + bb.y, 0.f);
    p.z = fmaxf(fmaf(acc.z, inv, self.z) + bb.z, 0.f);
    p.w = fmaxf(fmaf(acc.w, inv, self.w) + bb.w, 0.f);
    float ss = p.x * p.x + p.y * p.y + p.z * p.z + p.w * p.w;
    #pragma unroll
    for (int o = 16; o > 0; o >>= 1) ss += __shfl_xor_sync(0xffffffffu, ss, o);
    float s = 1.f / fmaxf(sqrtf(ss), 1e-12f);
    p.x *= s; p.y *= s; p.z *= s; p.w *= s;
    *(float4*)(g_H1 + (size_t)n * Ee + c4) = p;
}

// ----- K3: gather h2 = [H1[node], agg(H1)/deg] for the batch (warp per node) -----
__global__ void gather2_kernel(const int* __restrict__ nodes) {
    int warp = (blockIdx.x * blockDim.x + threadIdx.x) >> 5;
    int lane = threadIdx.x & 31;
    if (warp >= Bb) return;
    int n = nodes[warp];
    int c4 = lane * 4;
    float4 self = *(const float4*)(g_H1 + (size_t)n * Ee + c4);
    *(float4*)(g_h2 + (size_t)warp * 256 + c4) = self;
    float d = g_deg[n];
    int c = (int)d; if (c > CAP) c = CAP;
    const int* nb = g_nbr + n * CAP;
    float4 acc = make_float4(0.f, 0.f, 0.f, 0.f);
    for (int t = 0; t < c; t++) {
        int j = __ldg(nb + t);
        float4 v = *(const float4*)(g_H1 + (size_t)j * Ee + c4);
        acc.x += v.x; acc.y += v.y; acc.z += v.z; acc.w += v.w;
    }
    float inv = 1.f / d;
    acc.x *= inv; acc.y *= inv; acc.z *= inv; acc.w *= inv;
    *(float4*)(g_h2 + (size_t)warp * 256 + 128 + c4) = acc;
}

// ----- K4: H2 = l2norm(relu(h2 @ W2^T + b2))   M=4096 N=128 K=256 -----
__global__ __launch_bounds__(256, 2)
void gemm2_kernel(const float* __restrict__ b2) {
    __shared__ __align__(16) float As[16][PADR];
    __shared__ __align__(16) float Bs[16][PADR];
    int tid = threadIdx.x;
    int tm = tid >> 4, tn = tid & 15;
    int row0 = blockIdx.y * 128;

    unsigned long long acc[8][4];
    #pragma unroll
    for (int i = 0; i < 8; i++)
        #pragma unroll
        for (int j = 0; j < 4; j++) acc[i][j] = 0ull;

    int lr  = tid >> 2;
    int lc  = (tid & 3) * 4;
    int bkk = tid >> 5;
    int bc  = (tid & 31) * 4;

    for (int k0 = 0; k0 < 256; k0 += 16) {
        #pragma unroll
        for (int h = 0; h < 2; h++) {
            int r = lr + h * 64;
            float4 v = *(const float4*)(g_h2 + (size_t)(row0 + r) * 256 + k0 + lc);
            As[lc + 0][r] = v.x; As[lc + 1][r] = v.y;
            As[lc + 2][r] = v.z; As[lc + 3][r] = v.w;
        }
        #pragma unroll
        for (int h = 0; h < 2; h++) {
            int kk = bkk + h * 8;
            *(float4*)&Bs[kk][bc] = *(const float4*)(g_W2t + (k0 + kk) * 128 + bc);
        }
        __syncthreads();
        #pragma unroll
        for (int kk = 0; kk < 16; kk++) {
            float4 a0 = *(float4*)&As[kk][tm * 8];
            float4 a1 = *(float4*)&As[kk][tm * 8 + 4];
            ulonglong2 b0 = *(ulonglong2*)&Bs[kk][tn * 4];
            ulonglong2 b1 = *(ulonglong2*)&Bs[kk][64 + tn * 4];
            unsigned long long pa[8];
            pa[0] = pk2(a0.x, a0.x); pa[1] = pk2(a0.y, a0.y);
            pa[2] = pk2(a0.z, a0.z); pa[3] = pk2(a0.w, a0.w);
            pa[4] = pk2(a1.x, a1.x); pa[5] = pk2(a1.y, a1.y);
            pa[6] = pk2(a1.z, a1.z); pa[7] = pk2(a1.w, a1.w);
            #pragma unroll
            for (int i = 0; i < 8; i++) {
                fma2(acc[i][0], pa[i], b0.x);
                fma2(acc[i][1], pa[i], b0.y);
                fma2(acc[i][2], pa[i], b1.x);
                fma2(acc[i][3], pa[i], b1.y);
            }
        }
        __syncthreads();
    }
    // epilogue: +b2, relu, l2norm per row (reduce across the 16 tn lanes), store
    float4 b2a = *(const float4*)(b2 + tn * 4);
    float4 b2b = *(const float4*)(b2 + 64 + tn * 4);
    #pragma unroll
    for (int i = 0; i < 8; i++) {
        float2 c0 = up2(acc[i][0]), c1 = up2(acc[i][1]);
        float2 c2 = up2(acc[i][2]), c3 = up2(acc[i][3]);
        float v[8];
        v[0] = fmaxf(c0.x + b2a.x, 0.f); v[1] = fmaxf(c0.y + b2a.y, 0.f);
        v[2] = fmaxf(c1.x + b2a.z, 0.f); v[3] = fmaxf(c1.y + b2a.w, 0.f);
        v[4] = fmaxf(c2.x + b2b.x, 0.f); v[5] = fmaxf(c2.y + b2b.y, 0.f);
        v[6] = fmaxf(c3.x + b2b.z, 0.f); v[7] = fmaxf(c3.y + b2b.w, 0.f);
        float ss = 0.f;
        #pragma unroll
        for (int q = 0; q < 8; q++) ss += v[q] * v[q];
        ss += __shfl_xor_sync(0xffffffffu, ss, 1);
        ss += __shfl_xor_sync(0xffffffffu, ss, 2);
        ss += __shfl_xor_sync(0xffffffffu, ss, 4);
        ss += __shfl_xor_sync(0xffffffffu, ss, 8);
        float s = 1.f / fmaxf(sqrtf(ss), 1e-12f);
        int r = row0 + tm * 8 + i;
        *(float4*)(g_H2 + (size_t)r * Ee + tn * 4)      = make_float4(v[0]*s, v[1]*s, v[2]*s, v[3]*s);
        *(float4*)(g_H2 + (size_t)r * Ee + 64 + tn * 4) = make_float4(v[4]*s, v[5]*s, v[6]*s, v[7]*s);
    }
}

// ----- K5: classifier + softmax (block per batch node) -----
__global__ void cls_kernel(const float* __restrict__ Wl1, const float* __restrict__ bl1,
                           const float* __restrict__ Wl2, const float* __restrict__ bl2,
                           float* __restrict__ out) {
    __shared__ __align__(16) float Hs[Ee];
    __shared__ __align__(16) float xs[LINn];
    __shared__ float ls[Cc];
    int b = blockIdx.x;
    int t = threadIdx.x;
    Hs[t] = g_H2[(size_t)b * Ee + t];
    __syncthreads();
    float acc = bl1[t];
    const float4* wr = (const float4*)(Wl1 + t * Ee);
    const float4* hr = (const float4*)Hs;
    #pragma unroll
    for (int k = 0; k < Ee / 4; k++) {
        float4 w = wr[k]; float4 h = hr[k];
        acc += w.x * h.x + w.y * h.y + w.z * h.z + w.w * h.w;
    }
    xs[t] = acc;
    __syncthreads();
    if (t < Cc) {
        float a2 = bl2[t];
        const float4* w2 = (const float4*)(Wl2 + t * LINn);
        const float4* xr = (const float4*)xs;
        #pragma unroll
        for (int k = 0; k < LINn / 4; k++) {
            float4 w = w2[k]; float4 h = xr[k];
            a2 += w.x * h.x + w.y * h.y + w.z * h.z + w.w * h.w;
        }
        ls[t] = a2;
    }
    __syncthreads();
    if (t < Cc) {
        float m = ls[0];
        #pragma unroll
        for (int i = 1; i < Cc; i++) m = fmaxf(m, ls[i]);
        float s = 0.f;
        #pragma unroll
        for (int i = 0; i < Cc; i++) s += expf(ls[i] - m);
        out[(size_t)b * Cc + t] = expf(ls[t] - m) / s;
    }
}

extern "C" void kernel_launch(void* const* d_in, const int* in_sizes, int n_in,
                              void* d_out, int out_size) {
    const int*   nodes = (const int*)  d_in[0];
    const float* adj   = (const float*)d_in[1];
    const float* data  = (const float*)d_in[2];
    const float* W1    = (const float*)d_in[3];
    const float* b1    = (const float*)d_in[4];
    const float* W2    = (const float*)d_in[5];
    const float* b2    = (const float*)d_in[6];
    const float* Wl1   = (const float*)d_in[7];
    const float* bl1   = (const float*)d_in[8];
    const float* Wl2   = (const float*)d_in[9];
    const float* bl2   = (const float*)d_in[10];
    float* out = (float*)d_out;

    prep_kernel<<<512, 256>>>(W1, W2);
    scan_gemm_kernel<<<Nn + 256, 256>>>(adj, data);   // GEMM blocks [0,256) overlap CSR scan
    agg1_kernel<<<Nn / 8, 256>>>(b1);
    gather2_kernel<<<Bb / 8, 256>>>(nodes);
    gemm2_kernel<<<dim3(1, 32), 256>>>(b2);
    cls_kernel<<<Bb, 128>>>(Wl1, bl1, Wl2, bl2, out);
}